// round 4
// baseline (speedup 1.0000x reference)
#include <cuda_runtime.h>
#include <cuda_fp16.h>
#include <cstdint>

// Problem constants
#define M_DIM   32
#define K_DIM   8192
#define N_DIM   8192
#define GROUP   128

#define NTILE   256            // n-columns per CTA
#define SPLITS  8              // split-K factor
#define KSPLIT  (K_DIM / SPLITS)       // 1024 k per CTA
#define NUM_KT  (KSPLIT / GROUP)       // 8 k-tiles of 128
#define THREADS 256            // 8 warps, each owns 32 n-columns
#define NTILES  (N_DIM / NTILE)        // 32

// Activation SMEM tile: [32 m][128 k] fp16, pitch 136 halves (272 B) to kill bank conflicts
#define APITCH  136
#define ABUF_HALVES (32 * APITCH)      // 4352 halves = 8704 B per buffer

// Split-K partials: [SPLITS][32][8192] fp32 (8 MB static device scratch)
__device__ float g_partial[SPLITS * M_DIM * N_DIM];

// lop3: (a & b) | c  -> immLut 0xEA
static __device__ __forceinline__ uint32_t lop3_and_or(uint32_t a, uint32_t b, uint32_t c) {
    uint32_t d;
    asm("lop3.b32 %0, %1, %2, %3, 0xEA;" : "=r"(d) : "r"(a), "r"(b), "r"(c));
    return d;
}

// Dequant one nibble-pair (k=2i, 2i+1) of qword q into half2 (q-8)*s.
// sh8 = 8*(lane&3).
// lo = (u & 0xF) | 0x64006400            -> low half2 lane = 1024 + q_even
// h  = ((u<<12) & 0x000F0000) | lo       -> high half2 lane = 1024 + q_odd (uncontaminated)
// Exact: 1024+q representable, (1024+q)-1032 exact, one fp16 rounding on *s.
static __device__ __forceinline__ uint32_t dq2(uint32_t q, uint32_t sh8, uint32_t s2,
                                               uint32_t c1032) {
    uint32_t u = q >> sh8;
    uint32_t lo = lop3_and_or(u, 0x0000000Fu, 0x64006400u);
    uint32_t h  = lop3_and_or(u << 12, 0x000F0000u, lo);
    half2 x = __hsub2(*reinterpret_cast<half2*>(&h), *reinterpret_cast<half2*>(&c1032));
    half2 r = __hmul2(x, *reinterpret_cast<half2*>(&s2));
    return *reinterpret_cast<uint32_t*>(&r);
}

static __device__ __forceinline__ void mma_16816(float& d0, float& d1, float& d2, float& d3,
                                                 uint32_t a0, uint32_t a1, uint32_t a2,
                                                 uint32_t a3, uint32_t b0, uint32_t b1) {
    asm volatile(
        "mma.sync.aligned.m16n8k16.row.col.f32.f16.f16.f32 "
        "{%0,%1,%2,%3}, {%4,%5,%6,%7}, {%8,%9}, {%0,%1,%2,%3};\n"
        : "+f"(d0), "+f"(d1), "+f"(d2), "+f"(d3)
        : "r"(a0), "r"(a1), "r"(a2), "r"(a3), "r"(b0), "r"(b1));
}

__global__ void __launch_bounds__(THREADS, 2)
marlin_w4a16_main(const float* __restrict__ A, const int* __restrict__ qw,
                  const float* __restrict__ scales) {
    __shared__ __align__(16) half as2[2][ABUF_HALVES];

    const int tid  = threadIdx.x;
    const int lane = tid & 31;
    const int warp = tid >> 5;             // 0..7
    const int lane4 = lane >> 2;           // 0..7
    const uint32_t sh8 = (lane & 3) * 8;

    const int nbase = blockIdx.x * NTILE;  // CTA n-range
    const int split = blockIdx.y;          // k-split index
    const int k0    = split * KSPLIT;

    // Per-warp n base; c0 = column this thread's a-frag row-0 maps to
    const int c0 = nbase + warp * 32 + lane4;

    // Staging coords (activations): 32 rows x 8 threads/row, 4 float4 each
    const int sm = tid >> 3;               // 0..31 (m row)
    const int sj = tid & 7;                // 0..7
    const float* a_row = A + (size_t)sm * K_DIM + k0;

    const uint32_t c1032 = 0x64086408u;    // half2(1032, 1032)

    // Accumulators: [a-frag f(2)][m-tile t(4)][4]
    float acc[2][4][4];
#pragma unroll
    for (int f = 0; f < 2; f++)
#pragma unroll
        for (int t = 0; t < 4; t++)
#pragma unroll
            for (int r = 0; r < 4; r++) acc[f][t][r] = 0.0f;

    const int* qcol = qw + c0;             // + row*N_DIM per k-row-of-8

#pragma unroll 1
    for (int kt = 0; kt < NUM_KT; kt++) {
        const int buf = kt & 1;

        // ---- stage activations: A[0:32][k0 + kt*128 .. +128) fp32 -> fp16 SMEM ----
        {
            const float* src = a_row + kt * GROUP;
            half* dst = &as2[buf][sm * APITCH];
#pragma unroll
            for (int r = 0; r < 4; r++) {
                float4 v = *reinterpret_cast<const float4*>(src + (sj + 8 * r) * 4);
                half2 h0 = __floats2half2_rn(v.x, v.y);
                half2 h1 = __floats2half2_rn(v.z, v.w);
                uint2 pk;
                pk.x = *reinterpret_cast<uint32_t*>(&h0);
                pk.y = *reinterpret_cast<uint32_t*>(&h1);
                *reinterpret_cast<uint2*>(dst + (sj + 8 * r) * 4) = pk;
            }
        }
        __syncthreads();

        // ---- per-group scales for this thread's 4 n-columns ----
        uint32_t s2[4];
        {
            const float* sp = scales + (size_t)(split * NUM_KT + kt) * N_DIM + c0;
#pragma unroll
            for (int r = 0; r < 4; r++) {
                half sh = __float2half_rn(sp[r * 8]);
                half2 p = __halves2half2(sh, sh);
                s2[r] = *reinterpret_cast<uint32_t*>(&p);
            }
        }

        const int qrow0 = (k0 + kt * GROUP) >> 3;   // first k-row-of-8 in this tile

        // ---- 8 chunks of k16 ----
#pragma unroll
        for (int ch = 0; ch < 8; ch++) {
            const int* qr0 = qcol + (size_t)(qrow0 + 2 * ch) * N_DIM;
            const int* qr1 = qr0 + N_DIM;
            // W loads (4-lane broadcast each): rows {kq,kq+1} x col offsets {0,8,16,24}
            uint32_t q00 = (uint32_t)qr0[0],  q01 = (uint32_t)qr0[8];
            uint32_t q02 = (uint32_t)qr0[16], q03 = (uint32_t)qr0[24];
            uint32_t q10 = (uint32_t)qr1[0],  q11 = (uint32_t)qr1[8];
            uint32_t q12 = (uint32_t)qr1[16], q13 = (uint32_t)qr1[24];

            // a-frags (dequant straight into fragment registers)
            uint32_t a[2][4];
            a[0][0] = dq2(q00, sh8, s2[0], c1032);   // row n,    k 0..1
            a[0][1] = dq2(q01, sh8, s2[1], c1032);   // row n+8
            a[0][2] = dq2(q10, sh8, s2[0], c1032);   // row n,    k 8..9
            a[0][3] = dq2(q11, sh8, s2[1], c1032);   // row n+8
            a[1][0] = dq2(q02, sh8, s2[2], c1032);
            a[1][1] = dq2(q03, sh8, s2[3], c1032);
            a[1][2] = dq2(q12, sh8, s2[2], c1032);
            a[1][3] = dq2(q13, sh8, s2[3], c1032);

            // b-frags from SMEM: B[k][m], col m = 8t + lane/4, k = ch*16 + 2(lane&3) (+8)
            uint32_t b[4][2];
            const half* bb = &as2[buf][(size_t)(ch * 16 + (lane & 3) * 2)];
#pragma unroll
            for (int t = 0; t < 4; t++) {
                const half* bp = bb + (8 * t + lane4) * APITCH;
                b[t][0] = *reinterpret_cast<const uint32_t*>(bp);
                b[t][1] = *reinterpret_cast<const uint32_t*>(bp + 8);
            }

#pragma unroll
            for (int f = 0; f < 2; f++)
#pragma unroll
                for (int t = 0; t < 4; t++)
                    mma_16816(acc[f][t][0], acc[f][t][1], acc[f][t][2], acc[f][t][3],
                              a[f][0], a[f][1], a[f][2], a[f][3], b[t][0], b[t][1]);
        }
    }

    // ---- epilogue: write split partials, D[n][m] frag -> partial[split][m][n] ----
    float* pbase = g_partial + (size_t)split * M_DIM * N_DIM;
#pragma unroll
    for (int f = 0; f < 2; f++) {
        const int n_r = nbase + warp * 32 + 16 * f + lane4;
#pragma unroll
        for (int t = 0; t < 4; t++) {
            const int m_c = 8 * t + 2 * (lane & 3);
            float* p = pbase + (size_t)m_c * N_DIM + n_r;
            p[0]            = acc[f][t][0];   // (n_r,   m_c)
            p[N_DIM]        = acc[f][t][1];   // (n_r,   m_c+1)
            p[8]            = acc[f][t][2];   // (n_r+8, m_c)
            p[N_DIM + 8]    = acc[f][t][3];   // (n_r+8, m_c+1)
        }
    }
}

__global__ void __launch_bounds__(256)
marlin_w4a16_reduce(const float* __restrict__ bias, float* __restrict__ out) {
    const int idx = blockIdx.x * 256 + threadIdx.x;   // 0 .. 32*8192-1, n fastest
    const int n = idx & (N_DIM - 1);
    float s = 0.0f;
#pragma unroll
    for (int sp = 0; sp < SPLITS; sp++)
        s += g_partial[(size_t)sp * M_DIM * N_DIM + idx];
    out[idx] = s + bias[n];
}

extern "C" void kernel_launch(void* const* d_in, const int* in_sizes, int n_in,
                              void* d_out, int out_size) {
    const float* A      = (const float*)d_in[0];
    const int*   qw     = (const int*)d_in[1];
    const float* scales = (const float*)d_in[2];
    const float* bias   = (const float*)d_in[3];
    float* out = (float*)d_out;

    dim3 grid(NTILES, SPLITS);
    marlin_w4a16_main<<<grid, THREADS>>>(A, qw, scales);
    marlin_w4a16_reduce<<<(M_DIM * N_DIM) / 256, 256>>>(bias, out);
}